// round 14
// baseline (speedup 1.0000x reference)
#include <cuda_runtime.h>

#define P 49152
#define J 16
#define DL 10
#define H 64
#define OUTN (3 * P)            // 147456 output elements
#define W2_JSTRIDE (3 * P * H)  // floats per j-slice of w2 = 9437184
#define TRP 8                   // row-pairs per tile
#define NTILES 2                // tiles per warp -> 32 outputs per warp

// ---------------------------------------------------------------------------
// Fused kernel: each block computes dh (16x64) into smem, then streams its
// w2 slice. w1 (151 KB) is L2-resident after the first block touches it, so
// the per-block prologue costs ~2-3 us of L2-latency compute, replacing the
// 8.6 us serialized dh_kernel launch + gap.
//
//   dh[j][h] = relu(w1·feat + b1) - relu(w1·zfeat + b1)
//   out[o] = iv[o] + 1e-3 * sum_j relu(mask[j,o/3]) * <dh[j,:], w2[j,o,:]>
//
// Main loop (identical to R13 winner): 16 lanes per w2 row, j-outer /
// row-pair-inner, TRP consecutive LDG.128s = 4 KB contiguous per j-burst.
// ---------------------------------------------------------------------------
__global__ void __launch_bounds__(256) laplacian_fused_kernel(
        const float* __restrict__ x,
        const float* __restrict__ iv,
        const float* __restrict__ latent,
        const float* __restrict__ mask,
        const float* __restrict__ w1,
        const float* __restrict__ b1,
        const float* __restrict__ w2,
        const int*   __restrict__ nidx,
        const float* __restrict__ nmask,
        float* __restrict__ out) {
    __shared__ float  sfeat[J * 27];    // masked neighbor pose features
    __shared__ float  slat[J * DL];     // latent codes
    __shared__ float4 sdh[J * H / 4];   // dh, 1024 floats = 4 KB

    int tid = threadIdx.x;

    // ---- prologue: build features, then dh ----
    for (int i = tid; i < J * 27; i += 256) {
        int j = i / 27;
        int q = i % 27;
        int k = q / 9;
        int t = q % 9;
        int src = __ldg(&nidx[j * 3 + k]);
        sfeat[i] = __ldg(&x[src * 9 + t]) * __ldg(&nmask[j * 3 + k]);
    }
    if (tid < J * DL)
        slat[tid] = __ldg(&latent[tid]);
    __syncthreads();

    #pragma unroll
    for (int e = 0; e < 4; ++e) {
        int idx = tid + e * 256;            // (j,h) flat index, 0..1023
        int j   = idx >> 6;
        const float* wrow = w1 + (size_t)idx * (27 + DL);

        float s0 = __ldg(&b1[idx]);
        #pragma unroll
        for (int d = 0; d < DL; ++d)
            s0 = fmaf(__ldg(&wrow[27 + d]), slat[j * DL + d], s0);

        float s1 = s0;
        #pragma unroll
        for (int i = 0; i < 27; ++i)
            s1 = fmaf(__ldg(&wrow[i]), sfeat[j * 27 + i], s1);

        ((float*)sdh)[idx] = fmaxf(s1, 0.f) - fmaxf(s0, 0.f);
    }
    __syncthreads();

    // ---- main streaming loop (R13 winner, unchanged) ----
    int warp = tid >> 5;
    int lane = tid & 31;
    int l    = lane & 15;      // column-chunk within the row
    int grp  = lane >> 4;      // 0 or 1: which row of the pair
    int obase = (blockIdx.x * 8 + warp) * (NTILES * 2 * TRP);  // 576 blocks

    #pragma unroll 1
    for (int tile = 0; tile < NTILES; ++tile) {
        int ob = obase + tile * (2 * TRP) + grp;  // group's first output in tile
        const float4* base =
            reinterpret_cast<const float4*>(w2) + (size_t)ob * (H / 4) + l;

        float acc[TRP];
        #pragma unroll
        for (int rp = 0; rp < TRP; ++rp) acc[rp] = 0.f;

        #pragma unroll 1
        for (int j = 0; j < J; ++j) {
            float4 dv = sdh[j * 16 + l];               // one LDS per j
            const float4* wj = base + (size_t)j * (W2_JSTRIDE / 4);
            #pragma unroll
            for (int rp = 0; rp < TRP; ++rp) {
                // rp offset = rp * 2 rows * 16 float4 = immediate (512 B apart)
                float4 wv = __ldg(wj + rp * 32);
                float  s  = fmaxf(__ldg(&mask[j * P + (ob + 2 * rp) / 3]), 0.f);
                float d;
                d = wv.x * dv.x;
                d = fmaf(wv.y, dv.y, d);
                d = fmaf(wv.z, dv.z, d);
                d = fmaf(wv.w, dv.w, d);
                acc[rp] = fmaf(s, d, acc[rp]);
            }
        }

        // reduce each accumulator across the 16 lanes of the group
        #pragma unroll
        for (int rp = 0; rp < TRP; ++rp) {
            float a = acc[rp];
            a += __shfl_xor_sync(0xffffffffu, a, 8);
            a += __shfl_xor_sync(0xffffffffu, a, 4);
            a += __shfl_xor_sync(0xffffffffu, a, 2);
            a += __shfl_xor_sync(0xffffffffu, a, 1);
            if (l == 0) {
                int og = ob + 2 * rp;
                out[og] = iv[og] + a * 1e-3f;
            }
        }
    }
}

// ---------------------------------------------------------------------------
// Launch. Inputs (metadata order):
//  0 x (144)  1 input_verts (147456)  2 latent_code (160)  3 mask_param (786432)
//  4 w1 (37888)  5 b1 (1024)  6 w2 (150994944)  7 b2 (unused)  8 neighbor_idxs (48 i32)
//  9 neighbor_mask (48)
// ---------------------------------------------------------------------------
extern "C" void kernel_launch(void* const* d_in, const int* in_sizes, int n_in,
                              void* d_out, int out_size) {
    const float* x      = (const float*)d_in[0];
    const float* iv     = (const float*)d_in[1];
    const float* latent = (const float*)d_in[2];
    const float* maskp  = (const float*)d_in[3];
    const float* w1     = (const float*)d_in[4];
    const float* b1     = (const float*)d_in[5];
    const float* w2     = (const float*)d_in[6];
    const int*   nidx   = (const int*)d_in[8];
    const float* nmask  = (const float*)d_in[9];
    float* out = (float*)d_out;

    laplacian_fused_kernel<<<OUTN / (8 * NTILES * 2 * TRP), 256>>>(
        x, iv, latent, maskp, w1, b1, w2, nidx, nmask, out);
}